// round 2
// baseline (speedup 1.0000x reference)
#include <cuda_runtime.h>
#include <cuda_bf16.h>
#include <math.h>

// ---------------- problem constants ----------------
#define LAYERS 8
#define NHEAD 8
#define EMB 768
#define VOCAB 32000
#define BATCH 4
#define SEQ 1024
#define HS 96            // EMB / NHEAD
#define FF 3072          // 4*EMB
#define BT (BATCH*SEQ)   // 4096

// ---------------- scratch (static device globals; no allocs allowed) ----------
__device__ __align__(128) float g_x [BT*EMB];
__device__ __align__(128) float g_xa[BT*EMB];
__device__ __align__(128) float g_q [BT*EMB];
__device__ __align__(128) float g_k [BT*EMB];
__device__ __align__(128) float g_v [BT*EMB];
__device__ __align__(128) float g_ao[BT*EMB];
__device__ __align__(128) float g_h [BT*FF];
__device__ __align__(128) float g_rowloss[BT];

// ---------------- reduction helpers ----------------
__device__ __forceinline__ float warpMax(float v){
#pragma unroll
    for (int o = 16; o > 0; o >>= 1) v = fmaxf(v, __shfl_xor_sync(0xffffffffu, v, o));
    return v;
}
__device__ __forceinline__ float warpSum(float v){
#pragma unroll
    for (int o = 16; o > 0; o >>= 1) v += __shfl_xor_sync(0xffffffffu, v, o);
    return v;
}
__device__ __forceinline__ float blockMax(float v, float* sh){
    int lane = threadIdx.x & 31, w = threadIdx.x >> 5, nw = blockDim.x >> 5;
    v = warpMax(v);
    __syncthreads();
    if (lane == 0) sh[w] = v;
    __syncthreads();
    v = (threadIdx.x < nw) ? sh[threadIdx.x] : -INFINITY;
    if (w == 0) v = warpMax(v);
    if (threadIdx.x == 0) sh[0] = v;
    __syncthreads();
    return sh[0];
}
__device__ __forceinline__ float blockSum(float v, float* sh){
    int lane = threadIdx.x & 31, w = threadIdx.x >> 5, nw = blockDim.x >> 5;
    v = warpSum(v);
    __syncthreads();
    if (lane == 0) sh[w] = v;
    __syncthreads();
    v = (threadIdx.x < nw) ? sh[threadIdx.x] : 0.f;
    if (w == 0) v = warpSum(v);
    if (threadIdx.x == 0) sh[0] = v;
    __syncthreads();
    return sh[0];
}

// ---------------- embedding ----------------
__global__ void embed_kernel(const int* __restrict__ idx,
                             const float* __restrict__ tok_emb,
                             const float* __restrict__ pos_emb,
                             float* __restrict__ out){
    int row = blockIdx.x;            // b*SEQ + t
    int t   = row % SEQ;
    int tok = idx[row];
    const float* te = tok_emb + (size_t)tok * EMB;
    const float* pe = pos_emb + (size_t)t   * EMB;
    float* o = out + (size_t)row * EMB;
    for (int e = threadIdx.x; e < EMB; e += blockDim.x)
        o[e] = te[e] + pe[e];
}

// ---------------- layernorm (one block per row) ----------------
__global__ void ln_kernel(const float* __restrict__ x,
                          const float* __restrict__ g,
                          const float* __restrict__ b,
                          float* __restrict__ y){
    __shared__ float sh[32];
    int row = blockIdx.x;
    const float* xr = x + (size_t)row * EMB;
    float s = 0.f, s2 = 0.f;
    for (int i = threadIdx.x; i < EMB; i += blockDim.x){
        float v = xr[i]; s += v; s2 += v * v;
    }
    s  = blockSum(s , sh);
    s2 = blockSum(s2, sh);
    float m   = s  * (1.f / EMB);
    float var = s2 * (1.f / EMB) - m * m;
    float inv = rsqrtf(var + 1e-5f);
    float* yr = y + (size_t)row * EMB;
    for (int i = threadIdx.x; i < EMB; i += blockDim.x)
        yr[i] = (xr[i] - m) * inv * g[i] + b[i];
}

// ---------------- generic SGEMM: C[M,N] = A[M,K] @ B[K,N] (+bias,+residual,gelu) -----
// All dims must be multiples: M%128==0, N%128==0 (and N%4), K%8==0. True for this net.
#define GBM 128
#define GBN 128
#define GBK 8
#define GTM 8
#define GTN 8

__device__ __forceinline__ float gelu_exact(float v){
    return 0.5f * v * (1.f + erff(v * 0.70710678118654752f));
}

__global__ __launch_bounds__(256) void gemm_nn(
    int M, int N, int K,
    const float* __restrict__ A, const float* __restrict__ B,
    const float* __restrict__ bias, const float* __restrict__ residual,
    float* __restrict__ C, int do_gelu)
{
    __shared__ float As[GBK][GBM];
    __shared__ float Bs[GBK][GBN];
    int tid = threadIdx.x;
    int tx = tid & 15;        // 0..15 (col groups)
    int ty = tid >> 4;        // 0..15 (row groups)
    const float* Ab = A + (size_t)blockIdx.y * GBM * K;
    const float* Bb = B + (size_t)blockIdx.x * GBN;
    int arow = tid >> 1;      int acol = (tid & 1) * 4;
    int brow = tid >> 5;      int bcol = (tid & 31) * 4;
    float acc[GTM][GTN] = {};
    for (int k0 = 0; k0 < K; k0 += GBK){
        float4 a4 = *reinterpret_cast<const float4*>(Ab + (size_t)arow * K + k0 + acol);
        As[acol+0][arow] = a4.x; As[acol+1][arow] = a4.y;
        As[acol+2][arow] = a4.z; As[acol+3][arow] = a4.w;
        float4 b4 = *reinterpret_cast<const float4*>(Bb + (size_t)(k0 + brow) * N + bcol);
        *reinterpret_cast<float4*>(&Bs[brow][bcol]) = b4;
        __syncthreads();
#pragma unroll
        for (int k = 0; k < GBK; k++){
            float am[GTM], bn[GTN];
#pragma unroll
            for (int i = 0; i < GTM; i++) am[i] = As[k][ty*GTM+i];
#pragma unroll
            for (int j = 0; j < GTN; j++) bn[j] = Bs[k][tx*GTN+j];
#pragma unroll
            for (int i = 0; i < GTM; i++)
#pragma unroll
                for (int j = 0; j < GTN; j++)
                    acc[i][j] += am[i] * bn[j];
        }
        __syncthreads();
    }
    int r0 = blockIdx.y * GBM + ty * GTM;
    int c0 = blockIdx.x * GBN + tx * GTN;
#pragma unroll
    for (int i = 0; i < GTM; i++){
        size_t roff = (size_t)(r0 + i) * N;
#pragma unroll
        for (int j = 0; j < GTN; j += 4){
            int c = c0 + j;
            float4 v;
            v.x = acc[i][j]; v.y = acc[i][j+1]; v.z = acc[i][j+2]; v.w = acc[i][j+3];
            if (bias){ v.x += bias[c]; v.y += bias[c+1]; v.z += bias[c+2]; v.w += bias[c+3]; }
            if (do_gelu){ v.x = gelu_exact(v.x); v.y = gelu_exact(v.y);
                          v.z = gelu_exact(v.z); v.w = gelu_exact(v.w); }
            if (residual){
                float4 rr = *reinterpret_cast<const float4*>(residual + roff + c);
                v.x += rr.x; v.y += rr.y; v.z += rr.z; v.w += rr.w;
            }
            *reinterpret_cast<float4*>(C + roff + c) = v;
        }
    }
}

// C[M,N] = A[M,K] @ B[N,K]^T  (for tied lm_head; B row-major [N,K])
__global__ __launch_bounds__(256) void gemm_nt(
    int M, int N, int K,
    const float* __restrict__ A, const float* __restrict__ B,
    float* __restrict__ C)
{
    __shared__ float As[GBK][GBM];
    __shared__ float Bs[GBK][GBN];
    int tid = threadIdx.x;
    int tx = tid & 15;
    int ty = tid >> 4;
    const float* Ab = A + (size_t)blockIdx.y * GBM * K;
    const float* Bb = B + (size_t)blockIdx.x * GBN * K;
    int arow = tid >> 1;  int acol = (tid & 1) * 4;
    float acc[GTM][GTN] = {};
    for (int k0 = 0; k0 < K; k0 += GBK){
        float4 a4 = *reinterpret_cast<const float4*>(Ab + (size_t)arow * K + k0 + acol);
        As[acol+0][arow] = a4.x; As[acol+1][arow] = a4.y;
        As[acol+2][arow] = a4.z; As[acol+3][arow] = a4.w;
        float4 b4 = *reinterpret_cast<const float4*>(Bb + (size_t)arow * K + k0 + acol);
        Bs[acol+0][arow] = b4.x; Bs[acol+1][arow] = b4.y;
        Bs[acol+2][arow] = b4.z; Bs[acol+3][arow] = b4.w;
        __syncthreads();
#pragma unroll
        for (int k = 0; k < GBK; k++){
            float am[GTM], bn[GTN];
#pragma unroll
            for (int i = 0; i < GTM; i++) am[i] = As[k][ty*GTM+i];
#pragma unroll
            for (int j = 0; j < GTN; j++) bn[j] = Bs[k][tx*GTN+j];
#pragma unroll
            for (int i = 0; i < GTM; i++)
#pragma unroll
                for (int j = 0; j < GTN; j++)
                    acc[i][j] += am[i] * bn[j];
        }
        __syncthreads();
    }
    int r0 = blockIdx.y * GBM + ty * GTM;
    int c0 = blockIdx.x * GBN + tx * GTN;
#pragma unroll
    for (int i = 0; i < GTM; i++){
        size_t roff = (size_t)(r0 + i) * N;
#pragma unroll
        for (int j = 0; j < GTN; j += 4){
            float4 v;
            v.x = acc[i][j]; v.y = acc[i][j+1]; v.z = acc[i][j+2]; v.w = acc[i][j+3];
            *reinterpret_cast<float4*>(C + roff + c0 + j) = v;
        }
    }
}

// ---------------- causal attention: one block per (b,h,t) row ----------------
__global__ __launch_bounds__(128) void attn_kernel(
    const float* __restrict__ q, const float* __restrict__ k,
    const float* __restrict__ v, float* __restrict__ o)
{
    __shared__ float qs[HS];
    __shared__ float sc[SEQ];
    __shared__ float red[32];
    int t  = blockIdx.x;
    int bh = blockIdx.y;
    int b  = bh / NHEAD, h = bh % NHEAD;
    int tid = threadIdx.x;
    const float scale = rsqrtf((float)HS);
    size_t base = (size_t)b * SEQ * EMB + (size_t)h * HS;

    if (tid < HS) qs[tid] = q[base + (size_t)t * EMB + tid] * scale;
    __syncthreads();

    float lmax = -INFINITY;
    for (int s = tid; s <= t; s += 128){
        const float* kr = k + base + (size_t)s * EMB;
        float d = 0.f;
#pragma unroll
        for (int e = 0; e < HS; e += 4){
            float4 kk = *reinterpret_cast<const float4*>(kr + e);
            d += qs[e]*kk.x + qs[e+1]*kk.y + qs[e+2]*kk.z + qs[e+3]*kk.w;
        }
        sc[s] = d;
        lmax = fmaxf(lmax, d);
    }
    lmax = blockMax(lmax, red);

    float lsum = 0.f;
    for (int s = tid; s <= t; s += 128){
        float p = expf(sc[s] - lmax);
        sc[s] = p;
        lsum += p;
    }
    lsum = blockSum(lsum, red);
    float inv = 1.f / lsum;

    for (int d0 = tid; d0 < HS; d0 += 128){
        float acc = 0.f;
        const float* vp = v + base + d0;
        for (int s = 0; s <= t; s++)
            acc += sc[s] * vp[(size_t)s * EMB];
        o[base + (size_t)t * EMB + d0] = acc * inv;
    }
}

// ---------------- loss ----------------
__global__ __launch_bounds__(256) void loss_row_kernel(
    const float* __restrict__ logits, const int* __restrict__ targets,
    float* __restrict__ rowloss)
{
    __shared__ float sh[32];
    int row = blockIdx.x;
    const float* lr = logits + (size_t)row * VOCAB;
    float lmax = -INFINITY;
    for (int i = threadIdx.x; i < VOCAB; i += 256) lmax = fmaxf(lmax, lr[i]);
    lmax = blockMax(lmax, sh);
    float lsum = 0.f;
    for (int i = threadIdx.x; i < VOCAB; i += 256) lsum += expf(lr[i] - lmax);
    lsum = blockSum(lsum, sh);
    if (threadIdx.x == 0)
        rowloss[row] = -(lr[targets[row]] - lmax - logf(lsum));
}

__global__ __launch_bounds__(256) void loss_reduce_kernel(
    const float* __restrict__ rowloss, float* __restrict__ out)
{
    __shared__ float sh[32];
    float s = 0.f;
    for (int i = threadIdx.x; i < BT; i += 256) s += rowloss[i];
    s = blockSum(s, sh);
    if (threadIdx.x == 0) out[0] = s * (1.f / BT);
}

// ---------------- launcher ----------------
extern "C" void kernel_launch(void* const* d_in, const int* in_sizes, int n_in,
                              void* d_out, int out_size)
{
    const int*   idx     = (const int*)  d_in[0];
    const int*   targets = (const int*)  d_in[1];
    const float* tok_emb = (const float*)d_in[2];
    const float* pos_emb = (const float*)d_in[3];
    const float* Wq      = (const float*)d_in[4];
    const float* Wk      = (const float*)d_in[5];
    const float* Wv      = (const float*)d_in[6];
    const float* Wo      = (const float*)d_in[7];
    const float* bo      = (const float*)d_in[8];
    const float* ln1_g   = (const float*)d_in[9];
    const float* ln1_b   = (const float*)d_in[10];
    const float* ln2_g   = (const float*)d_in[11];
    const float* ln2_b   = (const float*)d_in[12];
    const float* W1      = (const float*)d_in[13];
    const float* b1      = (const float*)d_in[14];
    const float* W2      = (const float*)d_in[15];
    const float* b2      = (const float*)d_in[16];
    const float* lnf_g   = (const float*)d_in[17];
    const float* lnf_b   = (const float*)d_in[18];
    float* out = (float*)d_out;

    void *px, *pxa, *pq, *pk, *pv, *pao, *ph, *prl;
    cudaGetSymbolAddress(&px,  g_x);
    cudaGetSymbolAddress(&pxa, g_xa);
    cudaGetSymbolAddress(&pq,  g_q);
    cudaGetSymbolAddress(&pk,  g_k);
    cudaGetSymbolAddress(&pv,  g_v);
    cudaGetSymbolAddress(&pao, g_ao);
    cudaGetSymbolAddress(&ph,  g_h);
    cudaGetSymbolAddress(&prl, g_rowloss);
    float* x  = (float*)px;   float* xa = (float*)pxa;
    float* q  = (float*)pq;   float* k  = (float*)pk;
    float* v  = (float*)pv;   float* ao = (float*)pao;
    float* hb = (float*)ph;   float* rl = (float*)prl;

    embed_kernel<<<BT, 256>>>(idx, tok_emb, pos_emb, x);

    dim3 gE(EMB / GBN, BT / GBM);    // N=768
    dim3 gF(FF  / GBN, BT / GBM);    // N=3072
    dim3 gV(VOCAB / GBN, BT / GBM);  // N=32000
    dim3 gAttn(SEQ, BATCH * NHEAD);

    for (int l = 0; l < LAYERS; l++){
        size_t wofs  = (size_t)l * EMB * EMB;
        size_t f1ofs = (size_t)l * EMB * FF;

        ln_kernel<<<BT, 256>>>(x, ln1_g + l*EMB, ln1_b + l*EMB, xa);
        gemm_nn<<<gE, 256>>>(BT, EMB, EMB, xa, Wq + wofs, nullptr, nullptr, q, 0);
        gemm_nn<<<gE, 256>>>(BT, EMB, EMB, xa, Wk + wofs, nullptr, nullptr, k, 0);
        gemm_nn<<<gE, 256>>>(BT, EMB, EMB, xa, Wv + wofs, nullptr, nullptr, v, 0);
        attn_kernel<<<gAttn, 128>>>(q, k, v, ao);
        // x = x + ao @ Wo + bo   (in-place residual: each element read+written by owner thread)
        gemm_nn<<<gE, 256>>>(BT, EMB, EMB, ao, Wo + wofs, bo + l*EMB, x, x, 0);

        ln_kernel<<<BT, 256>>>(x, ln2_g + l*EMB, ln2_b + l*EMB, xa);
        gemm_nn<<<gF, 256>>>(BT, FF, EMB, xa, W1 + f1ofs, b1 + l*FF, nullptr, hb, 1);
        gemm_nn<<<gE, 256>>>(BT, EMB, FF, hb, W2 + f1ofs, b2 + l*EMB, x, x, 0);
    }

    ln_kernel<<<BT, 256>>>(x, lnf_g, lnf_b, xa);
    gemm_nt<<<gV, 256>>>(BT, VOCAB, EMB, xa, tok_emb, out);

    loss_row_kernel<<<BT, 256>>>(out, targets, rl);
    long long n_logits = (long long)BT * VOCAB;
    if ((long long)out_size > n_logits)
        loss_reduce_kernel<<<1, 256>>>(rl, out + n_logits);
}

// round 4
// speedup vs baseline: 2.7454x; 2.7454x over previous
#include <cuda_runtime.h>
#include <cuda_bf16.h>
#include <math.h>

// ---------------- problem constants ----------------
#define LAYERS 8
#define NHEAD 8
#define EMB 768
#define VOCAB 32000
#define BATCH 4
#define SEQ 1024
#define HS 96            // EMB / NHEAD
#define FF 3072          // 4*EMB
#define BT (BATCH*SEQ)   // 4096

// ---------------- scratch (static device globals; no allocs allowed) ----------
__device__ __align__(128) float g_x  [BT*EMB];
__device__ __align__(128) float g_xa [BT*EMB];
__device__ __align__(128) float g_q  [BT*EMB];
__device__ __align__(128) float g_k  [BT*EMB];
__device__ __align__(128) float g_v  [BT*EMB];
__device__ __align__(128) float g_ao [BT*EMB];
__device__ __align__(128) float g_h  [BT*FF];
__device__ __align__(128) float g_rowloss[BT];
// transposed weights: all GEMMs become C = A[M,K] * Bt[N,K]^T
__device__ __align__(128) float g_wqT[LAYERS*EMB*EMB];
__device__ __align__(128) float g_wkT[LAYERS*EMB*EMB];
__device__ __align__(128) float g_wvT[LAYERS*EMB*EMB];
__device__ __align__(128) float g_woT[LAYERS*EMB*EMB];
__device__ __align__(128) float g_w1T[LAYERS*EMB*FF];
__device__ __align__(128) float g_w2T[LAYERS*EMB*FF];

// ---------------- reduction helpers ----------------
__device__ __forceinline__ float warpMax(float v){
#pragma unroll
    for (int o = 16; o > 0; o >>= 1) v = fmaxf(v, __shfl_xor_sync(0xffffffffu, v, o));
    return v;
}
__device__ __forceinline__ float warpSum(float v){
#pragma unroll
    for (int o = 16; o > 0; o >>= 1) v += __shfl_xor_sync(0xffffffffu, v, o);
    return v;
}
__device__ __forceinline__ float blockMax(float v, float* sh){
    int lane = threadIdx.x & 31, w = threadIdx.x >> 5, nw = blockDim.x >> 5;
    v = warpMax(v);
    __syncthreads();
    if (lane == 0) sh[w] = v;
    __syncthreads();
    v = (threadIdx.x < nw) ? sh[threadIdx.x] : -INFINITY;
    if (w == 0) v = warpMax(v);
    if (threadIdx.x == 0) sh[0] = v;
    __syncthreads();
    return sh[0];
}
__device__ __forceinline__ float blockSum(float v, float* sh){
    int lane = threadIdx.x & 31, w = threadIdx.x >> 5, nw = blockDim.x >> 5;
    v = warpSum(v);
    __syncthreads();
    if (lane == 0) sh[w] = v;
    __syncthreads();
    v = (threadIdx.x < nw) ? sh[threadIdx.x] : 0.f;
    if (w == 0) v = warpSum(v);
    if (threadIdx.x == 0) sh[0] = v;
    __syncthreads();
    return sh[0];
}

// ---------------- embedding ----------------
__global__ void embed_kernel(const int* __restrict__ idx,
                             const float* __restrict__ tok_emb,
                             const float* __restrict__ pos_emb,
                             float* __restrict__ out){
    int row = blockIdx.x;            // b*SEQ + t
    int t   = row % SEQ;
    int tok = idx[row];
    const float* te = tok_emb + (size_t)tok * EMB;
    const float* pe = pos_emb + (size_t)t   * EMB;
    float* o = out + (size_t)row * EMB;
    for (int e = threadIdx.x; e < EMB; e += blockDim.x)
        o[e] = te[e] + pe[e];
}

// ---------------- layernorm (one block per row) ----------------
__global__ void ln_kernel(const float* __restrict__ x,
                          const float* __restrict__ g,
                          const float* __restrict__ b,
                          float* __restrict__ y){
    __shared__ float sh[32];
    int row = blockIdx.x;
    const float* xr = x + (size_t)row * EMB;
    float s = 0.f, s2 = 0.f;
    for (int i = threadIdx.x; i < EMB; i += blockDim.x){
        float v = xr[i]; s += v; s2 += v * v;
    }
    s  = blockSum(s , sh);
    s2 = blockSum(s2, sh);
    float m   = s  * (1.f / EMB);
    float var = s2 * (1.f / EMB) - m * m;
    float inv = rsqrtf(var + 1e-5f);
    float* yr = y + (size_t)row * EMB;
    for (int i = threadIdx.x; i < EMB; i += blockDim.x)
        yr[i] = (xr[i] - m) * inv * g[i] + b[i];
}

// ---------------- weight transpose: out[n][k] = in[k][n] ----------------
__global__ void transpose_kernel(const float* __restrict__ in, float* __restrict__ out,
                                 int K, int N){
    __shared__ float tile[32][33];
    const float* inm = in + (size_t)blockIdx.z * K * N;
    float* outm = out + (size_t)blockIdx.z * K * N;
    int n0 = blockIdx.x * 32, k0 = blockIdx.y * 32;
#pragma unroll
    for (int i = threadIdx.y; i < 32; i += 8)
        tile[i][threadIdx.x] = inm[(size_t)(k0 + i) * N + n0 + threadIdx.x];
    __syncthreads();
#pragma unroll
    for (int i = threadIdx.y; i < 32; i += 8)
        outm[(size_t)(n0 + i) * K + k0 + threadIdx.x] = tile[threadIdx.x][i];
}

// ---------------- TF32 tensor-core GEMM: C[M,N] = A[M,K] @ Bt[N,K]^T -------------
// BM=BN=128, BK=32. 256 threads = 8 warps in 4(m)x2(n); warp tile 32x64.
// mma.sync.m16n8k8 tf32, ldmatrix-fed, padded smem stride 36 floats (conflict-free).
#define TBM 128
#define TBN 128
#define TBK 32
#define SSTR 36

__device__ __forceinline__ unsigned f2tf(float f){
    unsigned u; asm("cvt.rna.tf32.f32 %0, %1;" : "=r"(u) : "f"(f)); return u;
}
__device__ __forceinline__ void ldsm4(unsigned* d, unsigned addr){
    asm volatile("ldmatrix.sync.aligned.m8n8.x4.shared.b16 {%0,%1,%2,%3}, [%4];"
        : "=r"(d[0]), "=r"(d[1]), "=r"(d[2]), "=r"(d[3]) : "r"(addr));
}
__device__ __forceinline__ void mma_tf32(float* c, const unsigned* a, unsigned b0, unsigned b1){
    asm volatile("mma.sync.aligned.m16n8k8.row.col.f32.tf32.tf32.f32 "
        "{%0,%1,%2,%3}, {%4,%5,%6,%7}, {%8,%9}, {%0,%1,%2,%3};"
        : "+f"(c[0]), "+f"(c[1]), "+f"(c[2]), "+f"(c[3])
        : "r"(a[0]), "r"(a[1]), "r"(a[2]), "r"(a[3]), "r"(b0), "r"(b1));
}
__device__ __forceinline__ float gelu_exact(float v){
    return 0.5f * v * (1.f + erff(v * 0.70710678118654752f));
}

__global__ __launch_bounds__(256) void gemm_tf32_nt(
    int M, int N, int K,
    const float* __restrict__ A, const float* __restrict__ B,   // B: [N][K]
    const float* __restrict__ bias, const float* __restrict__ residual,
    float* __restrict__ C, int do_gelu)
{
    __shared__ unsigned As[TBM * SSTR];
    __shared__ unsigned Bs[TBN * SSTR];
    int tid = threadIdx.x, lane = tid & 31, warp = tid >> 5;
    int wm = warp >> 1, wn = warp & 1;
    const float* Ab = A + (size_t)blockIdx.y * TBM * K;
    const float* Bb = B + (size_t)blockIdx.x * TBN * K;

    unsigned sa = (unsigned)__cvta_generic_to_shared(As);
    unsigned sb = (unsigned)__cvta_generic_to_shared(Bs);

    // loader: idx = tid + i*256 -> row = idx>>3 (0..127), chunk = idx&7 (4 floats each)
    int lr = tid >> 3, lc = tid & 7;

    float4 pa[4], pb[4];
#pragma unroll
    for (int i = 0; i < 4; i++){
        int r = lr + i * 32;
        pa[i] = *reinterpret_cast<const float4*>(Ab + (size_t)r * K + lc * 4);
        pb[i] = *reinterpret_cast<const float4*>(Bb + (size_t)r * K + lc * 4);
    }

    float acc[2][8][4];
#pragma unroll
    for (int i = 0; i < 2; i++)
#pragma unroll
        for (int j = 0; j < 8; j++)
#pragma unroll
            for (int e = 0; e < 4; e++) acc[i][j][e] = 0.f;

    int nk = K / TBK;
    for (int kt = 0; kt < nk; kt++){
#pragma unroll
        for (int i = 0; i < 4; i++){
            int r = lr + i * 32;
            unsigned* as = &As[r * SSTR + lc * 4];
            as[0] = f2tf(pa[i].x); as[1] = f2tf(pa[i].y);
            as[2] = f2tf(pa[i].z); as[3] = f2tf(pa[i].w);
            unsigned* bs = &Bs[r * SSTR + lc * 4];
            bs[0] = f2tf(pb[i].x); bs[1] = f2tf(pb[i].y);
            bs[2] = f2tf(pb[i].z); bs[3] = f2tf(pb[i].w);
        }
        __syncthreads();
        if (kt + 1 < nk){
            int k0 = (kt + 1) * TBK;
#pragma unroll
            for (int i = 0; i < 4; i++){
                int r = lr + i * 32;
                pa[i] = *reinterpret_cast<const float4*>(Ab + (size_t)r * K + k0 + lc * 4);
                pb[i] = *reinterpret_cast<const float4*>(Bb + (size_t)r * K + k0 + lc * 4);
            }
        }
#pragma unroll
        for (int s = 0; s < 4; s++){
            unsigned af[2][4], bf[4][4];
#pragma unroll
            for (int i = 0; i < 2; i++){
                int r  = wm * 32 + i * 16 + ((lane >> 3) & 1) * 8 + (lane & 7);
                int fo = s * 8 + (lane >> 4) * 4;
                ldsm4(af[i], sa + (unsigned)(r * SSTR + fo) * 4u);
            }
#pragma unroll
            for (int j = 0; j < 4; j++){
                int r  = wn * 64 + j * 16 + (lane >> 4) * 8 + (lane & 7);
                int fo = s * 8 + ((lane >> 3) & 1) * 4;
                ldsm4(bf[j], sb + (unsigned)(r * SSTR + fo) * 4u);
            }
#pragma unroll
            for (int i = 0; i < 2; i++)
#pragma unroll
                for (int j = 0; j < 4; j++){
                    mma_tf32(acc[i][2*j  ], af[i], bf[j][0], bf[j][1]);
                    mma_tf32(acc[i][2*j+1], af[i], bf[j][2], bf[j][3]);
                }
        }
        __syncthreads();
    }

    // epilogue
    int rb = blockIdx.y * TBM + wm * 32 + (lane >> 2);
    int cb = blockIdx.x * TBN + wn * 64 + (lane & 3) * 2;
#pragma unroll
    for (int i = 0; i < 2; i++){
#pragma unroll
        for (int jj = 0; jj < 8; jj++){
            int col = cb + jj * 8;
#pragma unroll
            for (int half = 0; half < 2; half++){
                int row = rb + i * 16 + half * 8;
                float vx = acc[i][jj][half*2], vy = acc[i][jj][half*2+1];
                if (bias){ vx += bias[col]; vy += bias[col+1]; }
                if (do_gelu){ vx = gelu_exact(vx); vy = gelu_exact(vy); }
                size_t off = (size_t)row * N + col;
                if (residual){
                    float2 rr = *reinterpret_cast<const float2*>(residual + off);
                    vx += rr.x; vy += rr.y;
                }
                float2 vv; vv.x = vx; vv.y = vy;
                *reinterpret_cast<float2*>(C + off) = vv;
            }
        }
    }
}

// ---------------- flash-style causal attention (fp32) ----------------
// Block: 256 threads, grid (SEQ/64, B*H). Tiles: 64 queries x 64 keys.
// Thread (tq = tid/4, g = tid%4): scores for s = g+4j (16), output dims g*24..g*24+23.
#define ATT 64
#define APD 100   // padded head-dim stride (floats)
#define APS 68    // padded score-row stride

__global__ __launch_bounds__(256) void attn2_kernel(
    const float* __restrict__ q, const float* __restrict__ k,
    const float* __restrict__ v, float* __restrict__ o)
{
    extern __shared__ float sm[];
    float* Qs = sm;                  // [64][APD]
    float* Ks = sm + 64 * APD;
    float* Vs = sm + 2 * 64 * APD;
    float* Ps = sm + 3 * 64 * APD;   // [64][APS]

    int tt = blockIdx.x;
    int bh = blockIdx.y;
    int b = bh >> 3, h = bh & 7;
    int tid = threadIdx.x;
    int tq = tid >> 2;   // 0..63
    int g  = tid & 3;    // 0..3
    size_t base = (size_t)b * SEQ * EMB + (size_t)h * HS;
    int t0 = tt * ATT;
    const float scale = rsqrtf((float)HS);

    // load Q tile (scaled)
    for (int i = tid; i < ATT * 24; i += 256){
        int r = i / 24, c4 = (i % 24) * 4;
        float4 qv = *reinterpret_cast<const float4*>(q + base + (size_t)(t0 + r) * EMB + c4);
        Qs[r * APD + c4 + 0] = qv.x * scale;
        Qs[r * APD + c4 + 1] = qv.y * scale;
        Qs[r * APD + c4 + 2] = qv.z * scale;
        Qs[r * APD + c4 + 3] = qv.w * scale;
    }
    float accd[24];
#pragma unroll
    for (int d = 0; d < 24; d++) accd[d] = 0.f;
    float mrow = -INFINITY, lrow = 0.f;
    __syncthreads();

    int dbase = g * 24;
    for (int st = 0; st <= tt; st++){
        int s0 = st * ATT;
        for (int i = tid; i < ATT * 24; i += 256){
            int r = i / 24, c4 = (i % 24) * 4;
            *reinterpret_cast<float4*>(Ks + r * APD + c4) =
                *reinterpret_cast<const float4*>(k + base + (size_t)(s0 + r) * EMB + c4);
            *reinterpret_cast<float4*>(Vs + r * APD + c4) =
                *reinterpret_cast<const float4*>(v + base + (size_t)(s0 + r) * EMB + c4);
        }
        __syncthreads();

        float sc[16];
#pragma unroll
        for (int j = 0; j < 16; j++) sc[j] = 0.f;
#pragma unroll 4
        for (int e = 0; e < HS; e += 4){
            float4 q4 = *reinterpret_cast<float4*>(Qs + tq * APD + e);
#pragma unroll
            for (int j = 0; j < 16; j++){
                int s = g + 4 * j;
                float4 k4 = *reinterpret_cast<float4*>(Ks + s * APD + e);
                sc[j] += q4.x * k4.x + q4.y * k4.y + q4.z * k4.z + q4.w * k4.w;
            }
        }
        if (st == tt){
#pragma unroll
            for (int j = 0; j < 16; j++)
                if (g + 4 * j > tq) sc[j] = -INFINITY;
        }
        float tmax = -INFINITY;
#pragma unroll
        for (int j = 0; j < 16; j++) tmax = fmaxf(tmax, sc[j]);
        tmax = fmaxf(tmax, __shfl_xor_sync(0xffffffffu, tmax, 1));
        tmax = fmaxf(tmax, __shfl_xor_sync(0xffffffffu, tmax, 2));
        float m_new = fmaxf(mrow, tmax);
        float alpha = __expf(mrow - m_new);
        float psum = 0.f;
#pragma unroll
        for (int j = 0; j < 16; j++){
            float p = __expf(sc[j] - m_new);
            Ps[tq * APS + g + 4 * j] = p;
            psum += p;
        }
        psum += __shfl_xor_sync(0xffffffffu, psum, 1);
        psum += __shfl_xor_sync(0xffffffffu, psum, 2);
        lrow = lrow * alpha + psum;
        mrow = m_new;
#pragma unroll
        for (int d = 0; d < 24; d++) accd[d] *= alpha;
        __syncthreads();

#pragma unroll 4
        for (int s = 0; s < ATT; s++){
            float p = Ps[tq * APS + s];
#pragma unroll
            for (int d4 = 0; d4 < 6; d4++){
                float4 vv = *reinterpret_cast<float4*>(Vs + s * APD + dbase + d4 * 4);
                accd[d4*4+0] += p * vv.x;
                accd[d4*4+1] += p * vv.y;
                accd[d4*4+2] += p * vv.z;
                accd[d4*4+3] += p * vv.w;
            }
        }
        __syncthreads();
    }

    float inv = 1.f / lrow;
    float* orow = (float*)(o + base + (size_t)(t0 + tq) * EMB + dbase);
#pragma unroll
    for (int d4 = 0; d4 < 6; d4++){
        float4 vv;
        vv.x = accd[d4*4+0] * inv; vv.y = accd[d4*4+1] * inv;
        vv.z = accd[d4*4+2] * inv; vv.w = accd[d4*4+3] * inv;
        *reinterpret_cast<float4*>(orow + d4 * 4) = vv;
    }
}

// ---------------- loss ----------------
__global__ __launch_bounds__(256) void loss_row_kernel(
    const float* __restrict__ logits, const int* __restrict__ targets,
    float* __restrict__ rowloss)
{
    __shared__ float sh[32];
    int row = blockIdx.x;
    const float* lr = logits + (size_t)row * VOCAB;
    float lmax = -INFINITY;
    for (int i = threadIdx.x; i < VOCAB; i += 256) lmax = fmaxf(lmax, lr[i]);
    lmax = blockMax(lmax, sh);
    float lsum = 0.f;
    for (int i = threadIdx.x; i < VOCAB; i += 256) lsum += expf(lr[i] - lmax);
    lsum = blockSum(lsum, sh);
    if (threadIdx.x == 0)
        rowloss[row] = -(lr[targets[row]] - lmax - logf(lsum));
}

__global__ __launch_bounds__(256) void loss_reduce_kernel(
    const float* __restrict__ rowloss, float* __restrict__ out)
{
    __shared__ float sh[32];
    float s = 0.f;
    for (int i = threadIdx.x; i < BT; i += 256) s += rowloss[i];
    s = blockSum(s, sh);
    if (threadIdx.x == 0) out[0] = s * (1.f / BT);
}

// ---------------- launcher ----------------
extern "C" void kernel_launch(void* const* d_in, const int* in_sizes, int n_in,
                              void* d_out, int out_size)
{
    const int*   idx     = (const int*)  d_in[0];
    const int*   targets = (const int*)  d_in[1];
    const float* tok_emb = (const float*)d_in[2];
    const float* pos_emb = (const float*)d_in[3];
    const float* Wq      = (const float*)d_in[4];
    const float* Wk      = (const float*)d_in[5];
    const float* Wv      = (const float*)d_in[6];
    const float* Wo      = (const float*)d_in[7];
    const float* bo      = (const float*)d_in[8];
    const float* ln1_g   = (const float*)d_in[9];
    const float* ln1_b   = (const float*)d_in[10];
    const float* ln2_g   = (const float*)d_in[11];
    const float* ln2_b   = (const float*)d_in[12];
    const float* W1      = (const float*)d_in[13];
    const float* b1      = (const float*)d_in[14];
    const float* W2      = (const float*)d_in[15];
    const float* b2      = (const float*)d_in[16];
    const float* lnf_g   = (const float*)d_in[17];
    const float* lnf_b   = (const float*)d_in[18];
    float* out = (float*)d_out;

    void *px, *pxa, *pq, *pk, *pv, *pao, *ph, *prl;
    void *pwq, *pwk, *pwv, *pwo, *pw1, *pw2;
    cudaGetSymbolAddress(&px,  g_x);
    cudaGetSymbolAddress(&pxa, g_xa);
    cudaGetSymbolAddress(&pq,  g_q);
    cudaGetSymbolAddress(&pk,  g_k);
    cudaGetSymbolAddress(&pv,  g_v);
    cudaGetSymbolAddress(&pao, g_ao);
    cudaGetSymbolAddress(&ph,  g_h);
    cudaGetSymbolAddress(&prl, g_rowloss);
    cudaGetSymbolAddress(&pwq, g_wqT);
    cudaGetSymbolAddress(&pwk, g_wkT);
    cudaGetSymbolAddress(&pwv, g_wvT);
    cudaGetSymbolAddress(&pwo, g_woT);
    cudaGetSymbolAddress(&pw1, g_w1T);
    cudaGetSymbolAddress(&pw2, g_w2T);
    float* x   = (float*)px;   float* xa  = (float*)pxa;
    float* q   = (float*)pq;   float* k   = (float*)pk;
    float* v   = (float*)pv;   float* ao  = (float*)pao;
    float* hb  = (float*)ph;   float* rl  = (float*)prl;
    float* wqT = (float*)pwq;  float* wkT = (float*)pwk;
    float* wvT = (float*)pwv;  float* woT = (float*)pwo;
    float* w1T = (float*)pw1;  float* w2T = (float*)pw2;

    static int smem_set = 0;
    // set every call (cheap, idempotent, capture-safe host-side call)
    cudaFuncSetAttribute(attn2_kernel, cudaFuncAttributeMaxDynamicSharedMemorySize, 96 * 1024);
    (void)smem_set;

    // weight transposes -> [N][K] layout
    dim3 tb(32, 8);
    transpose_kernel<<<dim3(EMB/32, EMB/32, LAYERS), tb>>>(Wq, wqT, EMB, EMB);
    transpose_kernel<<<dim3(EMB/32, EMB/32, LAYERS), tb>>>(Wk, wkT, EMB, EMB);
    transpose_kernel<<<dim3(EMB/32, EMB/32, LAYERS), tb>>>(Wv, wvT, EMB, EMB);
    transpose_kernel<<<dim3(EMB/32, EMB/32, LAYERS), tb>>>(Wo, woT, EMB, EMB);
    transpose_kernel<<<dim3(FF/32,  EMB/32, LAYERS), tb>>>(W1, w1T, EMB, FF);   // [768][3072] -> [3072][768]
    transpose_kernel<<<dim3(EMB/32, FF/32,  LAYERS), tb>>>(W2, w2T, FF, EMB);   // [3072][768] -> [768][3072]

    embed_kernel<<<BT, 256>>>(idx, tok_emb, pos_emb, x);

    dim3 gE(EMB / TBN, BT / TBM);    // N=768
    dim3 gF(FF  / TBN, BT / TBM);    // N=3072
    dim3 gV(VOCAB / TBN, BT / TBM);  // N=32000
    dim3 gAttn(SEQ / ATT, BATCH * NHEAD);
    int attn_smem = (3 * 64 * APD + 64 * APS) * 4;

    for (int l = 0; l < LAYERS; l++){
        size_t wofs  = (size_t)l * EMB * EMB;
        size_t f1ofs = (size_t)l * EMB * FF;

        ln_kernel<<<BT, 256>>>(x, ln1_g + l*EMB, ln1_b + l*EMB, xa);
        gemm_tf32_nt<<<gE, 256>>>(BT, EMB, EMB, xa, wqT + wofs, nullptr, nullptr, q, 0);
        gemm_tf32_nt<<<gE, 256>>>(BT, EMB, EMB, xa, wkT + wofs, nullptr, nullptr, k, 0);
        gemm_tf32_nt<<<gE, 256>>>(BT, EMB, EMB, xa, wvT + wofs, nullptr, nullptr, v, 0);
        attn2_kernel<<<gAttn, 256, attn_smem>>>(q, k, v, ao);
        gemm_tf32_nt<<<gE, 256>>>(BT, EMB, EMB, ao, woT + wofs, bo + l*EMB, x, x, 0);

        ln_kernel<<<BT, 256>>>(x, ln2_g + l*EMB, ln2_b + l*EMB, xa);
        gemm_tf32_nt<<<gF, 256>>>(BT, FF, EMB, xa, w1T + f1ofs, b1 + l*FF, nullptr, hb, 1);
        gemm_tf32_nt<<<gE, 256>>>(BT, EMB, FF, hb, w2T + f1ofs, b2 + l*EMB, x, x, 0);
    }

    ln_kernel<<<BT, 256>>>(x, lnf_g, lnf_b, xa);
    gemm_tf32_nt<<<gV, 256>>>(BT, VOCAB, EMB, xa, tok_emb, nullptr, nullptr, out, 0);

    loss_row_kernel<<<BT, 256>>>(out, targets, rl);
    long long n_logits = (long long)BT * VOCAB;
    if ((long long)out_size > n_logits)
        loss_reduce_kernel<<<1, 256>>>(rl, out + n_logits);
}